// round 17
// baseline (speedup 1.0000x reference)
#include <cuda_runtime.h>
#include <cuda_bf16.h>

// Levinson-Durbin, M=24. ONE row per thread; warp-autonomous 32-row tiles.
// out[row] = [K, a0..a23],  R a = -r1,  K = sqrt(E_24).
//
// R16 = best-of-breed: R8 shell (best timed: TPB=64, warp-private tiles,
// 56-reg cap, fine CTAs -> wave backfill) x R13 math (best ncu: serial dot
// m<=11, 2-way split m>=12 -> minimum fma-pipe ops).
// Established by experiment: one-row-per-thread is the register-stable
// basin; occupancy beyond ~38% buys nothing; single-wave fat CTAs lose to
// backfilled fine CTAs; packing/interleaving/bulk-copy all regress.

constexpr int M_ORD = 24;
constexpr int NC    = M_ORD + 1;               // 25
constexpr int TPB   = 64;
constexpr int WARPS = TPB / 32;                // 2
constexpr int ROWS_PER_WARP = 32;
constexpr int RPB   = TPB;                     // 64 rows per CTA (32/warp)
constexpr int WTILE_FLOATS = ROWS_PER_WARP * NC;   // 800
constexpr int WTILE_V4     = WTILE_FLOATS / 4;     // 200

__device__ __forceinline__ void cp_async16(unsigned saddr, const void* gaddr) {
    asm volatile("cp.async.cg.shared.global [%0], [%1], 16;"
                 :: "r"(saddr), "l"(gaddr));
}
__device__ __forceinline__ void cp_commit() {
    asm volatile("cp.async.commit_group;");
}
template <int N>
__device__ __forceinline__ void cp_wait() {
    asm volatile("cp.async.wait_group %0;" :: "n"(N));
}
// -(1/x): negation folded into the MUFU operand
__device__ __forceinline__ float nrcp(float x) {
    float y; asm("rcp.approx.f32 %0, %1;" : "=f"(y) : "f"(-x)); return y;
}
__device__ __forceinline__ float fsqrt_fast(float x) {
    float y; asm("sqrt.approx.f32 %0, %1;" : "=f"(y) : "f"(x)); return y;
}

// Full Levinson-Durbin recursion; returns K = sqrt(E_M), fills a[0..23].
// Minimal fma-pipe op count: serial dot m<=11, 2-way split m>=12.
__device__ __forceinline__ float levdur(const float rr[NC], float a[M_ORD]) {
    float E     = rr[0];
    float ninvE = nrcp(E);                     // -1/E, pipelined one iter ahead
    #pragma unroll
    for (int m = 0; m < M_ORD; m++) {
        float acc;
        if (m <= 11) {
            // serial single accumulator: zero join overhead
            float s0 = rr[m + 1];
            #pragma unroll
            for (int i = 0; i < m; i++) s0 = fmaf(a[i], rr[m - i], s0);
            acc = s0;
        } else {
            // 2-way split: one join FADD, chain <= ~12 dependent FMAs
            float s0 = rr[m + 1], s1 = 0.0f;
            #pragma unroll
            for (int i = 0; i + 1 < m; i += 2) {
                s0 = fmaf(a[i    ], rr[m - i    ], s0);
                s1 = fmaf(a[i + 1], rr[m - i - 1], s1);
            }
            if (m & 1) s0 = fmaf(a[m - 1], rr[1], s0);
            acc = s0 + s1;
        }

        float k = acc * ninvE;                 // k = -acc/E (MUFU latency hidden)

        // symmetric in-place update: a_i' = a_i + k * a_{m-1-i}
        #pragma unroll
        for (int i = 0; i < m / 2; i++) {
            float t = a[i];
            float u = a[m - 1 - i];
            a[i]         = fmaf(k, u, t);
            a[m - 1 - i] = fmaf(k, t, u);
        }
        if (m & 1) {
            float t = a[m / 2];
            a[m / 2] = fmaf(k, t, t);
        }
        a[m] = k;

        E     = fmaf(k, acc, E);               // E *= (1 - k^2)
        ninvE = nrcp(E);                       // hides under next dot
    }
    return fsqrt_fast(E);
}

__global__ __launch_bounds__(TPB, 18)          // caps regs at 56 (R8 optimum)
void levinson_durbin_kernel(const float* __restrict__ r,
                            float* __restrict__ out,
                            int nrows)
{
    __shared__ float sbuf[WARPS][WTILE_FLOATS];   // 6.4 KB per CTA
    const int lane = threadIdx.x & 31;
    const int wid  = threadIdx.x >> 5;
    const int wrow0 = blockIdx.x * RPB + wid * ROWS_PER_WARP;

    float rr[NC];
    float a[M_ORD];

    if (wrow0 + ROWS_PER_WARP <= nrows) {
        // ---- warp-private async prefetch of its 32-row tile ----
        unsigned s = (unsigned)__cvta_generic_to_shared(&sbuf[wid][0]);
        const float4* g = reinterpret_cast<const float4*>(r + (size_t)wrow0 * NC);
        #pragma unroll
        for (int i = lane; i < WTILE_V4; i += 32) cp_async16(s + i * 16, g + i);
        cp_commit();
        cp_wait<0>();
        __syncwarp();

        // stride-25 (odd) per-thread reads: bank-conflict-free
        #pragma unroll
        for (int i = 0; i < NC; i++) rr[i] = sbuf[wid][lane * NC + i];

        float Kv = levdur(rr, a);

        // stage output into own row (owner-only writes)
        sbuf[wid][lane * NC + 0] = Kv;
        #pragma unroll
        for (int i = 0; i < M_ORD; i++) sbuf[wid][lane * NC + 1 + i] = a[i];
        __syncwarp();

        // warp-private coalesced vector store
        float4* o = reinterpret_cast<float4*>(out + (size_t)wrow0 * NC);
        const float4* sb = reinterpret_cast<const float4*>(&sbuf[wid][0]);
        #pragma unroll
        for (int i = lane; i < WTILE_V4; i += 32) o[i] = sb[i];
    } else {
        // generic tail path (not hit for BATCH=262144)
        int row = wrow0 + lane;
        if (row < nrows) {
            #pragma unroll
            for (int i = 0; i < NC; i++) rr[i] = r[(size_t)row * NC + i];
            float Kv = levdur(rr, a);
            out[(size_t)row * NC + 0] = Kv;
            #pragma unroll
            for (int i = 0; i < M_ORD; i++)
                out[(size_t)row * NC + 1 + i] = a[i];
        }
    }
}

extern "C" void kernel_launch(void* const* d_in, const int* in_sizes, int n_in,
                              void* d_out, int out_size)
{
    const float* r = (const float*)d_in[0];
    float* out = (float*)d_out;
    const int nrows = in_sizes[0] / NC;
    const int grid = (nrows + RPB - 1) / RPB;
    levinson_durbin_kernel<<<grid, TPB>>>(r, out, nrows);
}